// round 1
// baseline (speedup 1.0000x reference)
#include <cuda_runtime.h>

#define BB 64
#define NN 1024
#define N_ITERS 20

// Scratch (allocation-free rule: static __device__ globals)
__device__ float g_E[(size_t)BB * NN * NN];   // exp(-C/eps), 256 MB
__device__ float g_wr[BB * NN];               // row scalings  exp(-r) = 1/rowsum
__device__ float g_wc[BB * NN];               // col scalings  exp(-c) = 1/colsum

// Accurate fast exp on the FMA pipe (avoids MUFU throughput wall).
// exp(x) = 2^(x*log2e); magic-number round, degree-6 Taylor of 2^f on [-0.5,0.5]
// (rel err ~1e-8), exponent spliced via integer add.
__device__ __forceinline__ float fexp(float x) {
    float y = x * 1.4426950408889634f;
    float t = y + 12582912.0f;                    // 1.5*2^23: round-to-nearest int
    int   n = __float_as_int(t) - 0x4B400000;     // signed integer part
    float f = y - (t - 12582912.0f);              // f in [-0.5, 0.5]
    float p = 1.5403530393e-4f;
    p = fmaf(p, f, 1.3333558146e-3f);
    p = fmaf(p, f, 9.6181291076e-3f);
    p = fmaf(p, f, 5.5504108665e-2f);
    p = fmaf(p, f, 2.4022650696e-1f);
    p = fmaf(p, f, 6.9314718056e-1f);
    p = fmaf(p, f, 1.0f);
    return __int_as_float(__float_as_int(p) + (n << 23));
}

// E = exp(-C/eps), grid-stride over float4
__global__ void k_init(const float* __restrict__ C, const float* __restrict__ eps) {
    float inv = -1.0f / eps[0];
    const float4* C4 = (const float4*)C;
    float4* E4 = (float4*)g_E;
    size_t n4 = (size_t)BB * NN * NN / 4;
    size_t stride = (size_t)gridDim.x * blockDim.x;
    for (size_t i = (size_t)blockIdx.x * blockDim.x + threadIdx.x; i < n4; i += stride) {
        float4 c = C4[i];
        float4 e;
        e.x = fexp(c.x * inv);
        e.y = fexp(c.y * inv);
        e.z = fexp(c.z * inv);
        e.w = fexp(c.w * inv);
        E4[i] = e;
    }
}

__global__ void k_wc_init() {
    int i = blockIdx.x * blockDim.x + threadIdx.x;
    if (i < BB * NN) g_wc[i] = 1.0f;
}

// wr[b,i] = 1 / sum_j E[b,i,j] * wc[b,j]   — one warp per row, float4 loads
__global__ void k_row() {
    int row  = blockIdx.x * 8 + (threadIdx.x >> 5);   // 65536 rows total
    int lane = threadIdx.x & 31;
    int b    = row >> 10;
    const float4* E4 = (const float4*)g_E + (size_t)row * (NN / 4);
    const float4* W4 = (const float4*)g_wc + b * (NN / 4);
    float acc = 0.0f;
#pragma unroll
    for (int it = 0; it < NN / 128; it++) {
        float4 e = E4[it * 32 + lane];
        float4 w = W4[it * 32 + lane];
        acc = fmaf(e.x, w.x, acc);
        acc = fmaf(e.y, w.y, acc);
        acc = fmaf(e.z, w.z, acc);
        acc = fmaf(e.w, w.w, acc);
    }
#pragma unroll
    for (int o = 16; o; o >>= 1) acc += __shfl_xor_sync(0xffffffffu, acc, o);
    if (lane == 0) g_wr[row] = 1.0f / acc;
}

// wc[b,j] = 1 / sum_i E[b,i,j] * wr[b,i]   — one thread per column,
// 128-col strips, wr staged in smem, 4 accumulators for MLP
__global__ void k_col() {
    __shared__ float s_wr[NN];
    int b = blockIdx.x >> 3;
    int j = (blockIdx.x & 7) * 128 + threadIdx.x;
    for (int i = threadIdx.x; i < NN; i += 128) s_wr[i] = g_wr[b * NN + i];
    __syncthreads();
    const float* Eb = g_E + (size_t)b * NN * NN + j;
    float a0 = 0.f, a1 = 0.f, a2 = 0.f, a3 = 0.f;
#pragma unroll 4
    for (int i = 0; i < NN; i += 4) {
        a0 = fmaf(Eb[(size_t)(i + 0) * NN], s_wr[i + 0], a0);
        a1 = fmaf(Eb[(size_t)(i + 1) * NN], s_wr[i + 1], a1);
        a2 = fmaf(Eb[(size_t)(i + 2) * NN], s_wr[i + 2], a2);
        a3 = fmaf(Eb[(size_t)(i + 3) * NN], s_wr[i + 3], a3);
    }
    g_wc[b * NN + j] = 1.0f / ((a0 + a1) + (a2 + a3));
}

// out = E * wr[i] * wc[j]
__global__ void k_final(float* __restrict__ out) {
    const float4* E4  = (const float4*)g_E;
    const float4* WC4 = (const float4*)g_wc;
    float4* O4 = (float4*)out;
    size_t n4 = (size_t)BB * NN * NN / 4;
    size_t stride = (size_t)gridDim.x * blockDim.x;
    for (size_t idx = (size_t)blockIdx.x * blockDim.x + threadIdx.x; idx < n4; idx += stride) {
        int j4   = (int)(idx & (NN / 4 - 1));
        int rest = (int)(idx >> 8);
        int i    = rest & (NN - 1);
        int b    = rest >> 10;
        float wr  = g_wr[b * NN + i];
        float4 wc = WC4[b * (NN / 4) + j4];
        float4 e  = E4[idx];
        float4 o;
        o.x = e.x * wr * wc.x;
        o.y = e.y * wr * wc.y;
        o.z = e.z * wr * wc.z;
        o.w = e.w * wr * wc.w;
        O4[idx] = o;
    }
}

extern "C" void kernel_launch(void* const* d_in, const int* in_sizes, int n_in,
                              void* d_out, int out_size) {
    const float* C   = (const float*)d_in[0];
    const float* eps = (const float*)d_in[1];
    float* out = (float*)d_out;

    k_init<<<2048, 256>>>(C, eps);
    k_wc_init<<<BB * NN / 256, 256>>>();
    for (int it = 0; it < N_ITERS; ++it) {
        k_row<<<BB * NN / 8, 256>>>();
        k_col<<<BB * 8, 128>>>();
    }
    k_final<<<2048, 256>>>(out);
}

// round 3
// speedup vs baseline: 1.7987x; 1.7987x over previous
#include <cuda_runtime.h>
#include <cuda_fp16.h>

#define BB 64
#define NN 1024
#define N_ITERS 20

// Scratch (allocation-free rule: static __device__ globals)
__device__ __half g_E [(size_t)BB * NN * NN];  // exp(-C/eps) fp16, 128 MB
__device__ __half g_ET[(size_t)BB * NN * NN];  // transposed copy,  128 MB
__device__ float  g_wr[BB * NN];               // row scalings  1/rowsum
__device__ float  g_wc[BB * NN];               // col scalings  1/colsum

// Fast exp on the FMA pipe (rel err ~1e-8 over our range).
__device__ __forceinline__ float fexp(float x) {
    float y = x * 1.4426950408889634f;
    float t = y + 12582912.0f;                    // 1.5*2^23 magic round
    int   n = __float_as_int(t) - 0x4B400000;
    float f = y - (t - 12582912.0f);              // f in [-0.5, 0.5]
    float p = 1.5403530393e-4f;
    p = fmaf(p, f, 1.3333558146e-3f);
    p = fmaf(p, f, 9.6181291076e-3f);
    p = fmaf(p, f, 5.5504108665e-2f);
    p = fmaf(p, f, 2.4022650696e-1f);
    p = fmaf(p, f, 6.9314718056e-1f);
    p = fmaf(p, f, 1.0f);
    return __int_as_float(__float_as_int(p) + (n << 23));
}

#define TR 64    // tile rows
#define TC 128   // tile cols

// E = exp(-C/eps) in fp16, plus transposed copy via smem tile.
__global__ void k_init(const float* __restrict__ C, const float* __restrict__ eps) {
    __shared__ __half s[TR][TC + 2];   // row stride 130 halves = 65 words (odd)
    float inv = -1.0f / eps[0];
    int b  = blockIdx.z;
    int r0 = blockIdx.y * TR;
    int c0 = blockIdx.x * TC;
    int lane = threadIdx.x & 31;
    int w    = threadIdx.x >> 5;       // 8 warps
    const size_t base = (size_t)b << 20;
    const float4* C4 = (const float4*)(C + base);
    __half* E  = g_E  + base;
    __half* ET = g_ET + base;

#pragma unroll
    for (int rr = w; rr < TR; rr += 8) {
        size_t r = (size_t)(r0 + rr);
        float4 v = C4[r * (NN / 4) + (c0 >> 2) + lane];
        __half h0 = __float2half_rn(fexp(v.x * inv));
        __half h1 = __float2half_rn(fexp(v.y * inv));
        __half h2 = __float2half_rn(fexp(v.z * inv));
        __half h3 = __float2half_rn(fexp(v.w * inv));
        __half2* Er = (__half2*)(E + r * NN + c0);
        Er[lane * 2 + 0] = __halves2half2(h0, h1);
        Er[lane * 2 + 1] = __halves2half2(h2, h3);
        s[rr][lane * 4 + 0] = h0;
        s[rr][lane * 4 + 1] = h1;
        s[rr][lane * 4 + 2] = h2;
        s[rr][lane * 4 + 3] = h3;
    }
    __syncthreads();
#pragma unroll
    for (int cc = w; cc < TC; cc += 8) {
        size_t j = (size_t)(c0 + cc);
        __half* Tr = ET + j * NN + r0;
        Tr[lane]      = s[lane][cc];
        Tr[lane + 32] = s[lane + 32][cc];
    }
}

__global__ void k_wc_init() {
    int i = blockIdx.x * blockDim.x + threadIdx.x;
    if (i < BB * NN) g_wc[i] = 1.0f;
}

// wout[b,r] = 1 / sum_k M[b,r,k] * win[b,k]
// One warp per row; win staged in smem (all 8 rows of a block share a batch).
// NOTE: M/win/wout are DEVICE-side references to __device__ globals, resolved
// inside device code via the thin wrappers below (passing __device__ symbols
// from host code is invalid — that was the round-2 bug).
__device__ __forceinline__ void pass_body(const __half* __restrict__ M,
                                          const float* __restrict__ win,
                                          float* __restrict__ wout) {
    __shared__ float s_win[NN];
    int row  = blockIdx.x * 8 + (threadIdx.x >> 5);
    int lane = threadIdx.x & 31;
    int b    = row >> 10;
    ((float4*)s_win)[threadIdx.x] = ((const float4*)(win + (b << 10)))[threadIdx.x];
    __syncthreads();
    const int4*   M4 = (const int4*)(M + ((size_t)row << 10));  // 128 int4 per row
    const float4* W4 = (const float4*)s_win;
    float acc = 0.0f;
#pragma unroll
    for (int it = 0; it < 4; it++) {
        int idx = it * 32 + lane;
        int4 ei = M4[idx];
        const __half2* h = (const __half2*)&ei;
        float4 wa = W4[idx * 2 + 0];
        float4 wb = W4[idx * 2 + 1];
        float2 f0 = __half22float2(h[0]);
        float2 f1 = __half22float2(h[1]);
        float2 f2 = __half22float2(h[2]);
        float2 f3 = __half22float2(h[3]);
        acc = fmaf(f0.x, wa.x, acc);
        acc = fmaf(f0.y, wa.y, acc);
        acc = fmaf(f1.x, wa.z, acc);
        acc = fmaf(f1.y, wa.w, acc);
        acc = fmaf(f2.x, wb.x, acc);
        acc = fmaf(f2.y, wb.y, acc);
        acc = fmaf(f3.x, wb.z, acc);
        acc = fmaf(f3.y, wb.w, acc);
    }
#pragma unroll
    for (int o = 16; o; o >>= 1) acc += __shfl_xor_sync(0xffffffffu, acc, o);
    if (lane == 0) wout[row] = 1.0f / acc;
}

__global__ void k_row() { pass_body(g_E,  g_wc, g_wr); }   // row normalize
__global__ void k_col() { pass_body(g_ET, g_wr, g_wc); }   // col normalize

// out = exp(-C/eps) * wr[i] * wc[j]  — exact fp32 path, no E array read.
__global__ void k_final(const float* __restrict__ C, const float* __restrict__ eps,
                        float* __restrict__ out) {
    float inv = -1.0f / eps[0];
    const float4* C4  = (const float4*)C;
    const float4* WC4 = (const float4*)g_wc;
    float4* O4 = (float4*)out;
    size_t n4 = (size_t)BB * NN * NN / 4;
    size_t stride = (size_t)gridDim.x * blockDim.x;
    for (size_t idx = (size_t)blockIdx.x * blockDim.x + threadIdx.x; idx < n4; idx += stride) {
        int j4   = (int)(idx & (NN / 4 - 1));
        int rest = (int)(idx >> 8);
        int i    = rest & (NN - 1);
        int b    = rest >> 10;
        float wr  = g_wr[b * NN + i];
        float4 wc = WC4[b * (NN / 4) + j4];
        float4 c  = C4[idx];
        float4 o;
        o.x = fexp(c.x * inv) * wr * wc.x;
        o.y = fexp(c.y * inv) * wr * wc.y;
        o.z = fexp(c.z * inv) * wr * wc.z;
        o.w = fexp(c.w * inv) * wr * wc.w;
        O4[idx] = o;
    }
}

extern "C" void kernel_launch(void* const* d_in, const int* in_sizes, int n_in,
                              void* d_out, int out_size) {
    const float* C   = (const float*)d_in[0];
    const float* eps = (const float*)d_in[1];
    float* out = (float*)d_out;

    dim3 ig(NN / TC, NN / TR, BB);   // (8, 16, 64)
    k_init<<<ig, 256>>>(C, eps);
    k_wc_init<<<BB * NN / 256, 256>>>();
    for (int it = 0; it < N_ITERS; ++it) {
        k_row<<<BB * NN / 8, 256>>>();
        k_col<<<BB * NN / 8, 256>>>();
    }
    k_final<<<2048, 256>>>(C, eps, out);
}

// round 6
// speedup vs baseline: 2.6781x; 1.4889x over previous
#include <cuda_runtime.h>
#include <cuda_fp16.h>
#include <cstdint>

#define BB 64
#define NN 1024
#define N_ITERS 20

// Scratch (allocation-free rule: static __device__ globals)
__device__ __half g_E[(size_t)BB * NN * NN];   // exp(-C/eps) fp16, 128 MB
__device__ float  g_wr[BB * NN];               // row scalings (last sweep)
__device__ float  g_wc[BB * NN];               // col scalings (final)
__device__ float  g_part[BB * 8 * NN];         // per-block colsum partials, 2 MB

// Fast exp on the FMA pipe (rel err ~1e-8 over our range).
__device__ __forceinline__ float fexp(float x) {
    float y = x * 1.4426950408889634f;
    float t = y + 12582912.0f;                    // 1.5*2^23 magic round
    int   n = __float_as_int(t) - 0x4B400000;
    float f = y - (t - 12582912.0f);              // f in [-0.5, 0.5]
    float p = 1.5403530393e-4f;
    p = fmaf(p, f, 1.3333558146e-3f);
    p = fmaf(p, f, 9.6181291076e-3f);
    p = fmaf(p, f, 5.5504108665e-2f);
    p = fmaf(p, f, 2.4022650696e-1f);
    p = fmaf(p, f, 6.9314718056e-1f);
    p = fmaf(p, f, 1.0f);
    return __int_as_float(__float_as_int(p) + (n << 23));
}

__device__ __forceinline__ unsigned h2_bits(__half2 h) {
    return *reinterpret_cast<unsigned*>(&h);
}

// E = exp(-C/eps) fp16, flat, 8 elements per thread per step
__global__ void k_init(const float* __restrict__ C, const float* __restrict__ eps) {
    float inv = -1.0f / eps[0];
    const float4* C4 = (const float4*)C;
    int4* E4 = (int4*)g_E;
    size_t n8 = (size_t)BB * NN * NN / 8;
    size_t stride = (size_t)gridDim.x * blockDim.x;
    for (size_t i = (size_t)blockIdx.x * blockDim.x + threadIdx.x; i < n8; i += stride) {
        float4 a = C4[2 * i];
        float4 b = C4[2 * i + 1];
        __half2 h0 = __floats2half2_rn(fexp(a.x * inv), fexp(a.y * inv));
        __half2 h1 = __floats2half2_rn(fexp(a.z * inv), fexp(a.w * inv));
        __half2 h2 = __floats2half2_rn(fexp(b.x * inv), fexp(b.y * inv));
        __half2 h3 = __floats2half2_rn(fexp(b.z * inv), fexp(b.w * inv));
        int4 o;
        o.x = (int)h2_bits(h0); o.y = (int)h2_bits(h1);
        o.z = (int)h2_bits(h2); o.w = (int)h2_bits(h3);
        E4[i] = o;
    }
}

__device__ __forceinline__ uint32_t smem_u32(const void* p) {
    return (uint32_t)__cvta_generic_to_shared(p);
}
#define CP16(dst, src) asm volatile("cp.async.cg.shared.global [%0], [%1], 16;" :: "r"(dst), "l"(src))
#define CP_COMMIT()    asm volatile("cp.async.commit_group;")
#define CP_WAIT(n)     asm volatile("cp.async.wait_group %0;" :: "n"(n))

// Fused Sinkhorn sweep: for each row i, wr_i = 1/sum_j E_ij*wc_j, then
// colacc_j += E_ij*wr_i. Block = 256 thr (8 warps), 128 rows of one batch.
// Column ownership: thread (w,l) owns the 4 columns j0..j0+3, j0 = w*128 + l*4
// (8 warps * 32 lanes * 4 = exactly 1024, no overlap — the round-5 OOB fix).
// E rows streamed through a 2-stage cp.async pipeline (8 rows / 16KB per stage).
template <bool FIRST>
__global__ void __launch_bounds__(256) k_sweep() {
    __shared__ __align__(16) __half s_tile[2][8 * NN];   // 32 KB
    __shared__ __align__(16) float  s_wc[NN];            // 4 KB
    __shared__ __align__(16) float  s_ps[8][8];          // row partials per warp
    int tid = threadIdx.x;
    int w = tid >> 5, l = tid & 31;
    int bi = blockIdx.x;
    int b = bi >> 3, blk = bi & 7;
    const __half* Ebase = g_E + ((size_t)b << 20) + ((size_t)blk << 17);  // rows blk*128..

    // Stage wc = 1 / (sum of previous sweep's 8 block partials)
    if (FIRST) {
        for (int i = tid; i < NN; i += 256) s_wc[i] = 1.0f;
    } else {
        const float* P = g_part + ((size_t)b << 13);
        for (int i = tid; i < NN; i += 256) {
            float s = 0.0f;
#pragma unroll
            for (int p = 0; p < 8; p++) s += P[(p << 10) + i];
            s_wc[i] = 1.0f / s;
        }
    }
    __syncthreads();

    int j0 = (w << 7) + (l << 2);          // 0..1020, exact cover
    float wcr[4];
    *(float4*)&wcr[0] = *(const float4*)&s_wc[j0];

    // cp.async stage issue: stage c = rows [c*8, c*8+8) = 16 KB contiguous
    auto issue = [&](int c, int slot) {
        const char* src = (const char*)Ebase + (size_t)c * 16384 + tid * 16;
        uint32_t dst = smem_u32(&s_tile[slot][0]) + tid * 16;
#pragma unroll
        for (int k = 0; k < 4; k++) CP16(dst + k * 4096, src + k * 4096);
        CP_COMMIT();
    };
    issue(0, 0);
    issue(1, 1);

    float acc[4] = {0.f, 0.f, 0.f, 0.f};

    for (int c = 0; c < 16; c++) {
        if (c < 14) { CP_WAIT(1); } else { CP_WAIT(0); }
        __syncthreads();   // publish stage data across threads

        const __half* tile = &s_tile[c & 1][0];
        float ev[8][4];
        // Phase A: load 8 rows' 4-col slices, convert once, dot with wc,
        // warp-reduce -> per-warp 128-col partial in s_ps[r][w]
#pragma unroll
        for (int r = 0; r < 8; r++) {
            int2 raw = *(const int2*)(tile + (r << 10) + j0);
            __half2* h = (__half2*)&raw;
            float2 f0 = __half22float2(h[0]);
            float2 f1 = __half22float2(h[1]);
            ev[r][0] = f0.x; ev[r][1] = f0.y; ev[r][2] = f1.x; ev[r][3] = f1.y;
            float s = 0.0f;
#pragma unroll
            for (int k = 0; k < 4; k++) s = fmaf(ev[r][k], wcr[k], s);
#pragma unroll
            for (int o = 16; o; o >>= 1) s += __shfl_xor_sync(0xffffffffu, s, o);
            if (l == 0) s_ps[r][w] = s;
        }
        __syncthreads();   // s_ps ready; also all reads of this tile slot done

        // Lanes 0..7 finalize wr for rows 0..7 of the chunk
        float wr_mine = 0.0f;
        if (l < 8) {
            float4 p0 = *(const float4*)&s_ps[l][0];
            float4 p1 = *(const float4*)&s_ps[l][4];
            wr_mine = 1.0f / (((p0.x + p0.y) + (p0.z + p0.w)) +
                              ((p1.x + p1.y) + (p1.z + p1.w)));
            if (w == 0) g_wr[(b << 10) + (blk << 7) + (c << 3) + l] = wr_mine;
        }
        // Phase B: colacc += E * wr (all from registers)
#pragma unroll
        for (int r = 0; r < 8; r++) {
            float wv = __shfl_sync(0xffffffffu, wr_mine, r);
#pragma unroll
            for (int k = 0; k < 4; k++) acc[k] = fmaf(ev[r][k], wv, acc[k]);
        }
        if (c + 2 < 16) issue(c + 2, c & 1);
    }

    // Write this block's colsum partial (j0 <= 1020, stays in block's 1024 slot)
    float* P = g_part + ((size_t)bi << 10) + j0;
    *(float4*)P = make_float4(acc[0], acc[1], acc[2], acc[3]);
}

// wc_j = 1 / sum of final sweep's partials
__global__ void k_wcfin() {
    int i = blockIdx.x * blockDim.x + threadIdx.x;   // 65536
    int b = i >> 10, j = i & (NN - 1);
    const float* P = g_part + ((size_t)b << 13) + j;
    float s = 0.0f;
#pragma unroll
    for (int p = 0; p < 8; p++) s += P[p << 10];
    g_wc[i] = 1.0f / s;
}

// out = exp(-C/eps) * wr[i] * wc[j]  — exact fp32 path
__global__ void k_final(const float* __restrict__ C, const float* __restrict__ eps,
                        float* __restrict__ out) {
    float inv = -1.0f / eps[0];
    const float4* C4  = (const float4*)C;
    const float4* WC4 = (const float4*)g_wc;
    float4* O4 = (float4*)out;
    size_t n4 = (size_t)BB * NN * NN / 4;
    size_t stride = (size_t)gridDim.x * blockDim.x;
    for (size_t idx = (size_t)blockIdx.x * blockDim.x + threadIdx.x; idx < n4; idx += stride) {
        int j4   = (int)(idx & (NN / 4 - 1));
        int rest = (int)(idx >> 8);
        int i    = rest & (NN - 1);
        int b    = rest >> 10;
        float wr  = g_wr[b * NN + i];
        float4 wc = WC4[b * (NN / 4) + j4];
        float4 c  = C4[idx];
        float4 o;
        o.x = fexp(c.x * inv) * wr * wc.x;
        o.y = fexp(c.y * inv) * wr * wc.y;
        o.z = fexp(c.z * inv) * wr * wc.z;
        o.w = fexp(c.w * inv) * wr * wc.w;
        O4[idx] = o;
    }
}

extern "C" void kernel_launch(void* const* d_in, const int* in_sizes, int n_in,
                              void* d_out, int out_size) {
    const float* C   = (const float*)d_in[0];
    const float* eps = (const float*)d_in[1];
    float* out = (float*)d_out;

    k_init<<<2048, 256>>>(C, eps);
    k_sweep<true><<<BB * 8, 256>>>();
    for (int t = 1; t < N_ITERS; ++t)
        k_sweep<false><<<BB * 8, 256>>>();
    k_wcfin<<<BB, 1024>>>();
    k_final<<<2048, 256>>>(C, eps, out);
}

// round 7
// speedup vs baseline: 2.9156x; 1.0887x over previous
#include <cuda_runtime.h>
#include <cuda_fp16.h>
#include <cstdint>

#define BB 64
#define NN 1024
#define N_ITERS 20

// Scratch (allocation-free rule: static __device__ globals)
__device__ __half g_E[(size_t)BB * NN * NN];   // exp(-C/eps) fp16, 128 MB
__device__ float  g_wr[BB * NN];               // row scalings (last sweep)
__device__ float  g_wc[BB * NN];               // col scalings (final)
__device__ float  g_part[BB * 8 * NN];         // per-block colsum partials, 2 MB

// Fast exp on the FMA pipe (rel err ~1e-8 over our range).
__device__ __forceinline__ float fexp(float x) {
    float y = x * 1.4426950408889634f;
    float t = y + 12582912.0f;                    // 1.5*2^23 magic round
    int   n = __float_as_int(t) - 0x4B400000;
    float f = y - (t - 12582912.0f);              // f in [-0.5, 0.5]
    float p = 1.5403530393e-4f;
    p = fmaf(p, f, 1.3333558146e-3f);
    p = fmaf(p, f, 9.6181291076e-3f);
    p = fmaf(p, f, 5.5504108665e-2f);
    p = fmaf(p, f, 2.4022650696e-1f);
    p = fmaf(p, f, 6.9314718056e-1f);
    p = fmaf(p, f, 1.0f);
    return __int_as_float(__float_as_int(p) + (n << 23));
}

__device__ __forceinline__ unsigned h2_bits(__half2 h) {
    return *reinterpret_cast<unsigned*>(&h);
}

// Warp-autonomous fused Sinkhorn sweep.
// Block = 256 thr (8 warps) handles 128 rows of one batch. Warp w owns rows
// [blk*128 + w*16, +16). Per row: rowsum (lane-local fma + butterfly), then
// colacc into register accumulators. Column ownership: lane l, k-group k owns
// cols [(k*32+l)*8, +8) -> acc[32]/lane covers all 1024 cols per warp exactly.
// No __syncthreads in the main loop. FIRST sweep fuses E = exp(-C/eps) compute.
template <bool FIRST>
__global__ void __launch_bounds__(256, 2) k_sweep(const float* __restrict__ C,
                                                  const float* __restrict__ eps) {
    __shared__ __align__(16) float s_wc[NN];        // 4 KB
    __shared__ __align__(16) float s_acc[8][NN];    // 32 KB
    int tid = threadIdx.x;
    int w = tid >> 5, l = tid & 31;
    int bi = blockIdx.x, b = bi >> 3, blk = bi & 7;

    float wcr[32];
    if (!FIRST) {
        const float* P = g_part + ((size_t)b << 13);
        for (int i = tid; i < NN; i += 256) {
            float s = 0.0f;
#pragma unroll
            for (int p = 0; p < 8; p++) s += P[(p << 10) + i];
            s_wc[i] = 1.0f / s;
        }
        __syncthreads();
#pragma unroll
        for (int k = 0; k < 4; k++) {
            *(float4*)&wcr[k * 8]     = *(const float4*)&s_wc[(k * 32 + l) * 8];
            *(float4*)&wcr[k * 8 + 4] = *(const float4*)&s_wc[(k * 32 + l) * 8 + 4];
        }
    }
    float inv = FIRST ? (-1.0f / eps[0]) : 0.0f;

    float acc[32];
#pragma unroll
    for (int k = 0; k < 32; k++) acc[k] = 0.0f;

    size_t rowbase = ((size_t)b << 10) + (blk << 7) + (w << 4);

    int4 raw[4], rawN[4];
    // Load / produce row 0
    if (FIRST) {
        const float4* Cr = (const float4*)(C + (rowbase << 10));
#pragma unroll
        for (int k = 0; k < 4; k++) {
            float4 a = Cr[(k * 32 + l) * 2];
            float4 c = Cr[(k * 32 + l) * 2 + 1];
            __half2 h0 = __floats2half2_rn(fexp(a.x * inv), fexp(a.y * inv));
            __half2 h1 = __floats2half2_rn(fexp(a.z * inv), fexp(a.w * inv));
            __half2 h2 = __floats2half2_rn(fexp(c.x * inv), fexp(c.y * inv));
            __half2 h3 = __floats2half2_rn(fexp(c.z * inv), fexp(c.w * inv));
            raw[k].x = (int)h2_bits(h0); raw[k].y = (int)h2_bits(h1);
            raw[k].z = (int)h2_bits(h2); raw[k].w = (int)h2_bits(h3);
        }
    } else {
        const int4* Er = (const int4*)(g_E + (rowbase << 10));
#pragma unroll
        for (int k = 0; k < 4; k++) raw[k] = Er[k * 32 + l];
    }

    for (int r = 0; r < 16; r++) {
        size_t row = rowbase + r;
        // Prefetch / produce next row (independent of this row's compute)
        if (r < 15) {
            if (FIRST) {
                const float4* Cr = (const float4*)(C + ((row + 1) << 10));
#pragma unroll
                for (int k = 0; k < 4; k++) {
                    float4 a = Cr[(k * 32 + l) * 2];
                    float4 c = Cr[(k * 32 + l) * 2 + 1];
                    __half2 h0 = __floats2half2_rn(fexp(a.x * inv), fexp(a.y * inv));
                    __half2 h1 = __floats2half2_rn(fexp(a.z * inv), fexp(a.w * inv));
                    __half2 h2 = __floats2half2_rn(fexp(c.x * inv), fexp(c.y * inv));
                    __half2 h3 = __floats2half2_rn(fexp(c.z * inv), fexp(c.w * inv));
                    rawN[k].x = (int)h2_bits(h0); rawN[k].y = (int)h2_bits(h1);
                    rawN[k].z = (int)h2_bits(h2); rawN[k].w = (int)h2_bits(h3);
                }
            } else {
                const int4* Er = (const int4*)(g_E + ((row + 1) << 10));
#pragma unroll
                for (int k = 0; k < 4; k++) rawN[k] = Er[k * 32 + l];
            }
        }
        if (FIRST) {   // persist E (coalesced 16B stores)
            int4* Er = (int4*)(g_E + (row << 10));
#pragma unroll
            for (int k = 0; k < 4; k++) Er[k * 32 + l] = raw[k];
        }
        // Phase A: rowsum over this lane's 32 cols, then butterfly reduce
        float sp[4] = {0.f, 0.f, 0.f, 0.f};
#pragma unroll
        for (int k = 0; k < 4; k++) {
            const __half2* h = (const __half2*)&raw[k];
#pragma unroll
            for (int m = 0; m < 4; m++) {
                float2 f = __half22float2(h[m]);
                if (FIRST) {
                    sp[k] += f.x + f.y;
                } else {
                    sp[k] = fmaf(f.x, wcr[k * 8 + 2 * m], sp[k]);
                    sp[k] = fmaf(f.y, wcr[k * 8 + 2 * m + 1], sp[k]);
                }
            }
        }
        float s = (sp[0] + sp[1]) + (sp[2] + sp[3]);
#pragma unroll
        for (int o = 16; o; o >>= 1) s += __shfl_xor_sync(0xffffffffu, s, o);
        float wr = 1.0f / s;
        if (l == 0) g_wr[row] = wr;
        // Phase B: colacc += E * wr (registers only; re-convert from raw)
#pragma unroll
        for (int k = 0; k < 4; k++) {
            const __half2* h = (const __half2*)&raw[k];
#pragma unroll
            for (int m = 0; m < 4; m++) {
                float2 f = __half22float2(h[m]);
                acc[k * 8 + 2 * m]     = fmaf(f.x, wr, acc[k * 8 + 2 * m]);
                acc[k * 8 + 2 * m + 1] = fmaf(f.y, wr, acc[k * 8 + 2 * m + 1]);
            }
        }
#pragma unroll
        for (int k = 0; k < 4; k++) raw[k] = rawN[k];
    }

    // Block colsum reduction: 8 warp-partials -> 1 block partial
#pragma unroll
    for (int k = 0; k < 4; k++) {
        *(float4*)&s_acc[w][(k * 32 + l) * 8]     = *(float4*)&acc[k * 8];
        *(float4*)&s_acc[w][(k * 32 + l) * 8 + 4] = *(float4*)&acc[k * 8 + 4];
    }
    __syncthreads();
    float4 sum = make_float4(0.f, 0.f, 0.f, 0.f);
#pragma unroll
    for (int p = 0; p < 8; p++) {
        float4 v = *(const float4*)&s_acc[p][tid * 4];
        sum.x += v.x; sum.y += v.y; sum.z += v.z; sum.w += v.w;
    }
    *(float4*)&g_part[((size_t)bi << 10) + tid * 4] = sum;
}

// wc_j = 1 / sum of final sweep's partials
__global__ void k_wcfin() {
    int i = blockIdx.x * blockDim.x + threadIdx.x;   // 65536
    int b = i >> 10, j = i & (NN - 1);
    const float* P = g_part + ((size_t)b << 13) + j;
    float s = 0.0f;
#pragma unroll
    for (int p = 0; p < 8; p++) s += P[p << 10];
    g_wc[i] = 1.0f / s;
}

// out = exp(-C/eps) * wr[i] * wc[j]  — exact fp32 path
__global__ void k_final(const float* __restrict__ C, const float* __restrict__ eps,
                        float* __restrict__ out) {
    float inv = -1.0f / eps[0];
    const float4* C4  = (const float4*)C;
    const float4* WC4 = (const float4*)g_wc;
    float4* O4 = (float4*)out;
    size_t n4 = (size_t)BB * NN * NN / 4;
    size_t stride = (size_t)gridDim.x * blockDim.x;
    for (size_t idx = (size_t)blockIdx.x * blockDim.x + threadIdx.x; idx < n4; idx += stride) {
        int j4   = (int)(idx & (NN / 4 - 1));
        int rest = (int)(idx >> 8);
        int i    = rest & (NN - 1);
        int b    = rest >> 10;
        float wr  = g_wr[b * NN + i];
        float4 wc = WC4[b * (NN / 4) + j4];
        float4 c  = C4[idx];
        float4 o;
        o.x = fexp(c.x * inv) * wr * wc.x;
        o.y = fexp(c.y * inv) * wr * wc.y;
        o.z = fexp(c.z * inv) * wr * wc.z;
        o.w = fexp(c.w * inv) * wr * wc.w;
        O4[idx] = o;
    }
}

extern "C" void kernel_launch(void* const* d_in, const int* in_sizes, int n_in,
                              void* d_out, int out_size) {
    const float* C   = (const float*)d_in[0];
    const float* eps = (const float*)d_in[1];
    float* out = (float*)d_out;

    k_sweep<true><<<BB * 8, 256>>>(C, eps);       // fused init + iteration 1
    for (int t = 1; t < N_ITERS; ++t)
        k_sweep<false><<<BB * 8, 256>>>(C, eps);
    k_wcfin<<<BB, 1024>>>();
    k_final<<<2048, 256>>>(C, eps, out);
}